// round 17
// baseline (speedup 1.0000x reference)
#include <cuda_runtime.h>
#include <cuda_bf16.h>
#include <math.h>
#include <stdint.h>

// ---------------- problem constants ----------------
#define NTOK   16384
#define EDIM   256
#define NE     8192
#define LAT    768
#define ODIM   768

#define OFF_ZQ     ((size_t)0)
#define OFF_IND    ((size_t)12582912)
#define OFF_LOSS   ((size_t)12599296)
#define OFF_EMB    ((size_t)12599297)
#define OFF_EAVG   ((size_t)14696449)
#define OFF_CS     ((size_t)16793601)
#define OFF_ENTMIN ((size_t)16801793)
#define OFF_COMMIT ((size_t)16801794)

#define QSCALE 126.0f
#define QINV   (1.0f / 126.0f)

// ---------------- device scratch ----------------
__device__ signed char g_d8[(size_t)NTOK * NE];
__device__ __nv_bfloat16 g_a[(size_t)NTOK * EDIM];
__device__ __nv_bfloat16 g_eh[(size_t)NE * EDIM];
__device__ __nv_bfloat16 g_el[(size_t)NE * EDIM];
__device__ __nv_bfloat16 g_wh[(size_t)ODIM * EDIM];
__device__ __nv_bfloat16 g_wl[(size_t)ODIM * EDIM];
__device__ float g_eproj[(size_t)NE * ODIM];
__device__ float g_xn[NTOK * EDIM];
__device__ float g_Sp[(size_t)64 * NTOK];
__device__ float g_Tp[(size_t)64 * NTOK];
__device__ int   g_Mp[(size_t)64 * NTOK];
__device__ float g_Sf[NTOK];
__device__ float g_Tf[NTOK];
__device__ int   g_Mf[NTOK];
__device__ unsigned long long g_mask[NTOK];
__device__ float g_invS[NTOK];
__device__ float g_bins[NE];
__device__ float g_ap[NE];
__device__ float g_cluster_new[NE];
__device__ int   g_expired[NE];
__device__ int   g_sampidx[NE];
__device__ float g_embed_sum[NE * EDIM];
__device__ float g_scal[4];

// ---------------- fast exp (FFMA only) ----------------
__device__ __forceinline__ float fast_exp(float x) {
    float z = x * 1.4426950408889634f;
    int   i = __float2int_rn(z);
    float rf = (float)i;
    float g = fmaf(rf, -0.693359375f, x);
    g = fmaf(rf, 2.12194440e-4f, g);
    float p = 1.98412698e-4f;
    p = fmaf(p, g, 1.38888889e-3f);
    p = fmaf(p, g, 8.33333333e-3f);
    p = fmaf(p, g, 4.16666667e-2f);
    p = fmaf(p, g, 1.66666667e-1f);
    p = fmaf(p, g, 0.5f);
    p = fmaf(p, g, 1.0f);
    p = fmaf(p, g, 1.0f);
    float sc = __int_as_float((i + 127) << 23);
    return p * sc;
}

// ---------------- helpers ----------------
__device__ __forceinline__ uint32_t smem_u32(const void* p) {
    uint32_t a;
    asm("{ .reg .u64 t; cvta.to.shared.u64 t, %1; cvt.u32.u64 %0, t; }" : "=r"(a) : "l"(p));
    return a;
}
__device__ __forceinline__ void ldsm4(uint32_t* r, uint32_t addr) {
    asm volatile("ldmatrix.sync.aligned.m8n8.x4.shared.b16 {%0,%1,%2,%3}, [%4];"
                 : "=r"(r[0]), "=r"(r[1]), "=r"(r[2]), "=r"(r[3]) : "r"(addr));
}
__device__ __forceinline__ void mma_bf16(float* c, const uint32_t* a, uint32_t b0, uint32_t b1) {
    asm volatile("mma.sync.aligned.m16n8k16.row.col.f32.bf16.bf16.f32 "
                 "{%0,%1,%2,%3}, {%4,%5,%6,%7}, {%8,%9}, {%0,%1,%2,%3};"
                 : "+f"(c[0]), "+f"(c[1]), "+f"(c[2]), "+f"(c[3])
                 : "r"(a[0]), "r"(a[1]), "r"(a[2]), "r"(a[3]), "r"(b0), "r"(b1));
}
__device__ __forceinline__ void cp16(uint32_t dst, const void* src) {
    asm volatile("cp.async.cg.shared.global [%0], [%1], 16;" :: "r"(dst), "l"(src));
}
#define CP_COMMIT() asm volatile("cp.async.commit_group;")

__device__ __forceinline__ int q8i(float d) {
    return __float2int_rn(fminf(fmaxf(d * QSCALE, -127.f), 127.f));
}

// ---------------- zeroing ----------------
__global__ void zero_kernel() {
    int i = blockIdx.x * 256 + threadIdx.x;
    if (i < NE * EDIM) g_embed_sum[i] = 0.f;
    if (i < NE)   { g_bins[i] = 0.f; g_ap[i] = 0.f; }
    if (i < 4)    g_scal[i] = 0.f;
}

// ---------------- fused in-proj GEMM + l2norm + bf16 (64x256 tile, full-N per CTA) ----------------
// xn = l2norm(x @ W_in^T + b_in); writes fp32 g_xn and bf16 g_a
__global__ void __launch_bounds__(256)
gemm_l2n_kernel(const float* __restrict__ A, const float* __restrict__ W,
                const float* __restrict__ bias,
                float* __restrict__ Xn, __nv_bfloat16* __restrict__ Xb) {
    __shared__ float As[2][8][68];
    __shared__ float Ws[2][8][260];
    const int tid = threadIdx.x;
    const int tx = tid & 31, ty = tid >> 5;
    const int bm = blockIdx.x * 64;
    const int K = LAT;
    float acc[8][8] = {};

    // loaders: A by tid<128 (64 rows x 2 float4), W by all (256 rows x 2 float4)
    const int arow = tid >> 1, alk = (tid & 1) * 4;           // tid<128
    const float* Ap = A + (size_t)(bm + arow) * K + alk;      // valid when tid<128
    const float* Wp = W + (size_t)tid * K;
    const int NIT = K >> 3;

    float4 av = (tid < 128) ? *(const float4*)(Ap) : make_float4(0.f, 0.f, 0.f, 0.f);
    float4 wv0 = *(const float4*)(Wp);
    float4 wv1 = *(const float4*)(Wp + 4);
    if (tid < 128) {
        As[0][alk+0][arow]=av.x; As[0][alk+1][arow]=av.y;
        As[0][alk+2][arow]=av.z; As[0][alk+3][arow]=av.w;
    }
    Ws[0][0][tid]=wv0.x; Ws[0][1][tid]=wv0.y; Ws[0][2][tid]=wv0.z; Ws[0][3][tid]=wv0.w;
    Ws[0][4][tid]=wv1.x; Ws[0][5][tid]=wv1.y; Ws[0][6][tid]=wv1.z; Ws[0][7][tid]=wv1.w;
    __syncthreads();

    for (int it = 0; it < NIT; it++) {
        int cur = it & 1;
        if (it + 1 < NIT) {
            if (tid < 128) av = *(const float4*)(Ap + (it + 1) * 8);
            wv0 = *(const float4*)(Wp + (it + 1) * 8);
            wv1 = *(const float4*)(Wp + (it + 1) * 8 + 4);
        }
#pragma unroll
        for (int k = 0; k < 8; k++) {
            float4 a0 = *(const float4*)&As[cur][k][ty * 8];
            float4 a1 = *(const float4*)&As[cur][k][ty * 8 + 4];
            float a[8] = {a0.x, a0.y, a0.z, a0.w, a1.x, a1.y, a1.z, a1.w};
            float b[8];
#pragma unroll
            for (int ic = 0; ic < 8; ic++) b[ic] = Ws[cur][k][ic * 32 + tx];
#pragma unroll
            for (int ir = 0; ir < 8; ir++)
#pragma unroll
                for (int ic = 0; ic < 8; ic++)
                    acc[ir][ic] = fmaf(a[ir], b[ic], acc[ir][ic]);
        }
        if (it + 1 < NIT) {
            int nxt = cur ^ 1;
            if (tid < 128) {
                As[nxt][alk+0][arow]=av.x; As[nxt][alk+1][arow]=av.y;
                As[nxt][alk+2][arow]=av.z; As[nxt][alk+3][arow]=av.w;
            }
            Ws[nxt][0][tid]=wv0.x; Ws[nxt][1][tid]=wv0.y; Ws[nxt][2][tid]=wv0.z; Ws[nxt][3][tid]=wv0.w;
            Ws[nxt][4][tid]=wv1.x; Ws[nxt][5][tid]=wv1.y; Ws[nxt][6][tid]=wv1.z; Ws[nxt][7][tid]=wv1.w;
        }
        __syncthreads();
    }

    // epilogue: bias, per-row l2norm via warp shuffle (row owned by one warp), dual store
    float bias_r[8];
#pragma unroll
    for (int ic = 0; ic < 8; ic++) bias_r[ic] = bias[ic * 32 + tx];
#pragma unroll
    for (int ir = 0; ir < 8; ir++) {
        int row = bm + ty * 8 + ir;
        float xp[8];
        float n2 = 0.f;
#pragma unroll
        for (int ic = 0; ic < 8; ic++) {
            xp[ic] = acc[ir][ic] + bias_r[ic];
            n2 = fmaf(xp[ic], xp[ic], n2);
        }
#pragma unroll
        for (int o = 16; o; o >>= 1) n2 += __shfl_xor_sync(0xffffffffu, n2, o);
        float nrm = sqrtf(n2);
#pragma unroll
        for (int ic = 0; ic < 8; ic++) {
            float xn = xp[ic] / nrm;
            Xn[(size_t)row * EDIM + ic * 32 + tx] = xn;
            Xb[(size_t)row * EDIM + ic * 32 + tx] = __float2bfloat16(xn);
        }
    }
}

// ---------------- fp32 -> bf16 hi/lo split ----------------
__global__ void conv_split_kernel(const float* __restrict__ src,
                                  __nv_bfloat16* __restrict__ hi,
                                  __nv_bfloat16* __restrict__ lo) {
    int i = blockIdx.x * 256 + threadIdx.x;
    float v[8];
    float4 v0 = ((const float4*)src)[2*i];
    float4 v1 = ((const float4*)src)[2*i+1];
    v[0]=v0.x; v[1]=v0.y; v[2]=v0.z; v[3]=v0.w;
    v[4]=v1.x; v[5]=v1.y; v[6]=v1.z; v[7]=v1.w;
    __nv_bfloat16 h[8], l[8];
#pragma unroll
    for (int j = 0; j < 8; j++) {
        h[j] = __float2bfloat16(v[j]);
        l[j] = __float2bfloat16(v[j] - __bfloat162float(h[j]));
    }
    uint4 ph, pl;
    ph.x = *(uint32_t*)&h[0]; ph.y = *(uint32_t*)&h[2];
    ph.z = *(uint32_t*)&h[4]; ph.w = *(uint32_t*)&h[6];
    pl.x = *(uint32_t*)&l[0]; pl.y = *(uint32_t*)&l[2];
    pl.z = *(uint32_t*)&l[4]; pl.w = *(uint32_t*)&l[6];
    ((uint4*)hi)[i] = ph;
    ((uint4*)lo)[i] = pl;
}

// ---------------- bf16 TC d-GEMM, 3-stage cp.async, int8-LUT epilogue ----------------
#define SSTP 72
#define STG  (128 * SSTP * 2)
#define NSTAGE 3
#define SMEM_MMA (NSTAGE * 2 * STG)    // 110592 B

__global__ void __launch_bounds__(256, 2)
mma_d_kernel() {
    extern __shared__ __align__(16) char smem[];
    const int tid = threadIdx.x;
    const int bm = blockIdx.y * 128, bn = blockIdx.x * 128;
    const int wid = tid >> 5, lane = tid & 31;
    const int wr = (wid & 1) * 64;
    const int wc = (wid >> 1) * 32;

    uint32_t sb = smem_u32(smem);
    uint32_t aOff = (uint32_t)(((wr + (lane & 15)) * SSTP + (lane >> 4) * 8) * 2);
    uint32_t bRow = (uint32_t)(wc + (lane & 7) + ((lane >> 4) << 3));
    uint32_t bOff = (uint32_t)((bRow * SSTP + ((lane >> 3) & 1) * 8) * 2);

    const char* gA = (const char*)g_a  + (size_t)bm * 512;
    const char* gB = (const char*)g_eh + (size_t)bn * 512;
    const int lrow = tid >> 3, lc8 = tid & 7;

    float acc[4][4][4] = {};

#pragma unroll
    for (int pc = 0; pc < 2; pc++) {
        uint32_t dstA = sb + (uint32_t)pc * 2 * STG;
        uint32_t dstB = dstA + STG;
#pragma unroll
        for (int j = 0; j < 4; j++) {
            int row = lrow + j * 32;
            uint32_t so = (uint32_t)((row * SSTP + lc8 * 8) * 2);
            cp16(dstA + so, gA + (size_t)row * 512 + pc * 128 + lc8 * 16);
            cp16(dstB + so, gB + (size_t)row * 512 + pc * 128 + lc8 * 16);
        }
        CP_COMMIT();
    }

#pragma unroll
    for (int kc = 0; kc < 4; kc++) {
        if (kc < 3) asm volatile("cp.async.wait_group 1;");
        else        asm volatile("cp.async.wait_group 0;");
        __syncthreads();
        if (kc + 2 < 4) {
            int st = (kc + 2) % NSTAGE;
            uint32_t dstA = sb + (uint32_t)st * 2 * STG;
            uint32_t dstB = dstA + STG;
#pragma unroll
            for (int j = 0; j < 4; j++) {
                int row = lrow + j * 32;
                uint32_t so = (uint32_t)((row * SSTP + lc8 * 8) * 2);
                cp16(dstA + so, gA + (size_t)row * 512 + (kc + 2) * 128 + lc8 * 16);
                cp16(dstB + so, gB + (size_t)row * 512 + (kc + 2) * 128 + lc8 * 16);
            }
            CP_COMMIT();
        }
        uint32_t stA = sb + (uint32_t)(kc % NSTAGE) * 2 * STG;
        uint32_t stB = stA + STG;
#pragma unroll
        for (int kk = 0; kk < 4; kk++) {
            uint32_t ko = (uint32_t)kk * 32;
            uint32_t aF[4][4], bF[2][4];
#pragma unroll
            for (int mi = 0; mi < 4; mi++) ldsm4(aF[mi], stA + aOff + mi * (16 * SSTP * 2) + ko);
#pragma unroll
            for (int n2 = 0; n2 < 2; n2++) ldsm4(bF[n2], stB + bOff + n2 * (16 * SSTP * 2) + ko);
#pragma unroll
            for (int mi = 0; mi < 4; mi++)
#pragma unroll
                for (int ni = 0; ni < 4; ni++)
                    mma_bf16(acc[mi][ni], aF[mi], bF[ni >> 1][(ni & 1) * 2], bF[ni >> 1][(ni & 1) * 2 + 1]);
        }
    }

    __syncthreads();

    // ---- int8-native epilogue: quantize, LUT S/T, int min, packed stores ----
    signed char* epi = (signed char*)smem;
    float* rS = (float*)(smem + 36864);
    float* rT = rS + 512;
    int*   rM = (int*)(rT + 512);
    float* lutS = (float*)(smem + 43008);
    float* lutT = lutS + 256;
    {
        int qv = (tid < 128) ? tid : tid - 256;
        float t10 = 10.f * (float)qv * QINV;
        float e = fast_exp(t10);
        lutS[tid] = e;
        lutT[tid] = e * t10;
    }
    __syncthreads();

    const int cg = wid >> 1;
    const int r0 = wr + (lane >> 2);
    const int c0 = wc + (lane & 3) * 2;
#pragma unroll
    for (int mi = 0; mi < 4; mi++) {
#pragma unroll
        for (int half = 0; half < 2; half++) {
            int rr = r0 + mi * 16 + half * 8;
            float S = 0.f, T = 0.f;
            int qm = 127;
#pragma unroll
            for (int ni = 0; ni < 4; ni++) {
                int q0 = q8i(acc[mi][ni][half*2]);
                int q1 = q8i(acc[mi][ni][half*2+1]);
                S += lutS[q0 & 255] + lutS[q1 & 255];
                T += lutT[q0 & 255] + lutT[q1 & 255];
                qm = min(qm, min(q0, q1));
                *(short*)(epi + rr * 144 + c0 + ni * 8) =
                    (short)((q0 & 0xff) | (q1 << 8));
            }
#pragma unroll
            for (int o = 1; o < 4; o <<= 1) {
                S += __shfl_xor_sync(0xffffffffu, S, o);
                T += __shfl_xor_sync(0xffffffffu, T, o);
                qm = min(qm, __shfl_xor_sync(0xffffffffu, qm, o));
            }
            if ((lane & 3) == 0) {
                rS[cg * 128 + rr] = S;
                rT[cg * 128 + rr] = T;
                rM[cg * 128 + rr] = qm;
            }
        }
    }
    __syncthreads();
    if (tid < 128) {
        float S = rS[tid] + rS[128 + tid] + rS[256 + tid] + rS[384 + tid];
        float T = rT[tid] + rT[128 + tid] + rT[256 + tid] + rT[384 + tid];
        int m = min(min(rM[tid], rM[128 + tid]), min(rM[256 + tid], rM[384 + tid]));
        size_t o = (size_t)blockIdx.x * NTOK + bm + tid;
        g_Sp[o] = S; g_Tp[o] = T; g_Mp[o] = m;
    }
#pragma unroll
    for (int j = 0; j < 4; j++) {
        int idx = j * 256 + tid;
        int row = idx >> 3, c16 = idx & 7;
        uint4 v = *(uint4*)(epi + row * 144 + c16 * 16);
        *(uint4*)(g_d8 + (size_t)(bm + row) * NE + bn + c16 * 16) = v;
    }
}

// ---------------- reduce partials + candidate block mask ----------------
__global__ void reduce_partials_kernel() {
    int r = blockIdx.x * 256 + threadIdx.x;
    float S = 0.f, T = 0.f;
    int m = 127;
#pragma unroll 8
    for (int b = 0; b < 64; b++) {
        size_t o = (size_t)b * NTOK + r;
        S += g_Sp[o];
        T += g_Tp[o];
        m = min(m, g_Mp[o]);
    }
    int qthr = min(m + 2, 127);
    unsigned long long mask = 0ULL;
#pragma unroll 8
    for (int b = 0; b < 64; b++) {
        if (g_Mp[(size_t)b * NTOK + r] <= qthr)
            mask |= (1ULL << b);
    }
    g_Sf[r] = S; g_Tf[r] = T; g_Mf[r] = qthr;
    g_mask[r] = mask;
    g_invS[r] = 1.0f / S;
}

// ---------------- bf16-split TC GEMM (cp.async pipeline): g_eproj = embed @ W_out^T ----------------
#define EPSTG (4 * STG)
#define SMEM_EP (2 * EPSTG)

__global__ void __launch_bounds__(256)
eproj_kernel() {
    extern __shared__ __align__(16) char smem[];
    const int tid = threadIdx.x;
    const int bm = blockIdx.y * 128, bn = blockIdx.x * 128;
    const int wid = tid >> 5, lane = tid & 31;
    const int wr = (wid & 1) * 64;
    const int wc = (wid >> 1) * 32;

    uint32_t sb = smem_u32(smem);
    uint32_t aOff = (uint32_t)(((wr + (lane & 15)) * SSTP + (lane >> 4) * 8) * 2);
    uint32_t bRow = (uint32_t)(wc + (lane & 7) + ((lane >> 4) << 3));
    uint32_t bOff = (uint32_t)((bRow * SSTP + ((lane >> 3) & 1) * 8) * 2);

    const char* gAh = (const char*)g_eh + (size_t)bm * 512;
    const char* gAl = (const char*)g_el + (size_t)bm * 512;
    const char* gBh = (const char*)g_wh + (size_t)bn * 512;
    const char* gBl = (const char*)g_wl + (size_t)bn * 512;
    const int lrow = tid >> 3, lc8 = tid & 7;

    float acc[4][4][4] = {};

#pragma unroll
    for (int pc = 0; pc < 2; pc++) {
        uint32_t st = sb + (uint32_t)pc * EPSTG;
#pragma unroll
        for (int j = 0; j < 4; j++) {
            int row = lrow + j * 32;
            uint32_t so = (uint32_t)((row * SSTP + lc8 * 8) * 2);
            size_t go = (size_t)row * 512 + pc * 128 + lc8 * 16;
            cp16(st + so,           gAh + go);
            cp16(st + STG + so,     gAl + go);
            cp16(st + 2 * STG + so, gBh + go);
            cp16(st + 3 * STG + so, gBl + go);
        }
        CP_COMMIT();
    }

#pragma unroll
    for (int kc = 0; kc < 4; kc++) {
        if (kc < 3) asm volatile("cp.async.wait_group 1;");
        else        asm volatile("cp.async.wait_group 0;");
        __syncthreads();
        uint32_t st = sb + (uint32_t)(kc & 1) * EPSTG;
        const uint32_t AH = st, AL = st + STG, BH = st + 2 * STG, BL = st + 3 * STG;
#pragma unroll
        for (int kk = 0; kk < 4; kk++) {
            uint32_t ko = (uint32_t)kk * 32;
            uint32_t ah[4][4], al[4][4], bh[2][4], bl[2][4];
#pragma unroll
            for (int mi = 0; mi < 4; mi++) {
                ldsm4(ah[mi], AH + aOff + mi * (16 * SSTP * 2) + ko);
                ldsm4(al[mi], AL + aOff + mi * (16 * SSTP * 2) + ko);
            }
#pragma unroll
            for (int n2 = 0; n2 < 2; n2++) {
                ldsm4(bh[n2], BH + bOff + n2 * (16 * SSTP * 2) + ko);
                ldsm4(bl[n2], BL + bOff + n2 * (16 * SSTP * 2) + ko);
            }
#pragma unroll
            for (int mi = 0; mi < 4; mi++)
#pragma unroll
                for (int ni = 0; ni < 4; ni++) {
                    uint32_t h0 = bh[ni >> 1][(ni & 1) * 2], h1 = bh[ni >> 1][(ni & 1) * 2 + 1];
                    uint32_t l0 = bl[ni >> 1][(ni & 1) * 2], l1 = bl[ni >> 1][(ni & 1) * 2 + 1];
                    mma_bf16(acc[mi][ni], ah[mi], h0, h1);
                    mma_bf16(acc[mi][ni], ah[mi], l0, l1);
                    mma_bf16(acc[mi][ni], al[mi], h0, h1);
                }
        }
        __syncthreads();
        if (kc + 2 < 4) {
            uint32_t st2 = sb + (uint32_t)(kc & 1) * EPSTG;
#pragma unroll
            for (int j = 0; j < 4; j++) {
                int row = lrow + j * 32;
                uint32_t so = (uint32_t)((row * SSTP + lc8 * 8) * 2);
                size_t go = (size_t)row * 512 + (kc + 2) * 128 + lc8 * 16;
                cp16(st2 + so,           gAh + go);
                cp16(st2 + STG + so,     gAl + go);
                cp16(st2 + 2 * STG + so, gBh + go);
                cp16(st2 + 3 * STG + so, gBl + go);
            }
            CP_COMMIT();
        }
    }

    __syncthreads();
    float* epi = (float*)smem;
    {
        const int r0 = wr + (lane >> 2);
        const int c0 = wc + (lane & 3) * 2;
#pragma unroll
        for (int mi = 0; mi < 4; mi++)
#pragma unroll
            for (int ni = 0; ni < 4; ni++) {
                int rr = r0 + mi * 16, cc = c0 + ni * 8;
                *(float2*)(epi + rr * 132 + cc) = make_float2(acc[mi][ni][0], acc[mi][ni][1]);
                *(float2*)(epi + (rr + 8) * 132 + cc) = make_float2(acc[mi][ni][2], acc[mi][ni][3]);
            }
    }
    __syncthreads();
#pragma unroll
    for (int j = 0; j < 16; j++) {
        int idx = j * 256 + tid;
        int row = idx >> 5, c4 = idx & 31;
        uint4 v = *(uint4*)(epi + row * 132 + c4 * 4);
        *(uint4*)(g_eproj + (size_t)(bm + row) * ODIM + bn + c4 * 4) = v;
    }
}

// ---------------- row finalize: masked candidate scan, exact argmin, fused gather ----------------
__global__ void __launch_bounds__(256)
row_finalize_kernel(const float* __restrict__ embed, const float* __restrict__ b_out,
                    float* __restrict__ out) {
    const int r = blockIdx.x, t = threadIdx.x;
    const int w = t >> 5, lane = t & 31;
    __shared__ float sxn[256];
    __shared__ float swred[8];
    __shared__ unsigned long long swbest[8];
    __shared__ int scnt;
    __shared__ int scand[64];
    __shared__ int sind;

    sxn[t] = g_xn[(size_t)r * EDIM + t];
    if (t == 0) scnt = 0;
    float Stot = g_Sf[r], Ttot = g_Tf[r];
    int qthr = g_Mf[r];
    unsigned long long mask = g_mask[r];
    __syncthreads();

    if (w == 0) {
        uint32_t thr4 = (uint32_t)(qthr & 0xff) * 0x01010101u;
        const uint32_t* dp = (const uint32_t*)(g_d8 + (size_t)r * NE);
        unsigned long long mk = mask;
        while (mk) {
            int b = __ffsll(mk) - 1;
            mk &= mk - 1;
            uint32_t u = dp[b * 32 + lane];
            uint32_t m = __vcmples4(u, thr4);
            if (m) {
#pragma unroll
                for (int by = 0; by < 4; by++)
                    if ((m >> (8 * by)) & 1) {
                        int p = atomicAdd(&scnt, 1);
                        if (p < 64) scand[p] = (b * 32 + lane) * 4 + by;
                    }
            }
        }
    }
    __syncthreads();
    int ncand = scnt < 64 ? scnt : 64;
    int ind;
    if (ncand == 1) {
        ind = scand[0];
    } else {
        unsigned long long best = ~0ULL;
        for (int i = w; i < ncand; i += 8) {
            int c = scand[i];
            const float* er = embed + (size_t)c * EDIM;
            float s = 0.f;
#pragma unroll
            for (int j = 0; j < 8; j++)
                s = fmaf(sxn[lane + j * 32], er[lane + j * 32], s);
#pragma unroll
            for (int o = 16; o; o >>= 1) s += __shfl_xor_sync(0xffffffffu, s, o);
            unsigned u = __float_as_uint(s);
            u = (u & 0x80000000u) ? ~u : (u | 0x80000000u);
            unsigned long long k = ((unsigned long long)u << 32) | (unsigned)c;
            if (k < best) best = k;
        }
        if (lane == 0) swbest[w] = best;
        __syncthreads();
        if (t == 0) {
            unsigned long long b = swbest[0];
#pragma unroll
            for (int j = 1; j < 8; j++) if (swbest[j] < b) b = swbest[j];
            sind = (int)(b & 0xffffffffu);
        }
        __syncthreads();
        ind = sind;
    }

    float xnv = sxn[t];
    float ev = embed[(size_t)ind * EDIM + t];
    float df = ev - xnv;
    atomicAdd(&g_embed_sum[(size_t)ind * EDIM + t], xnv);
    float cs = df * df;
#pragma unroll
    for (int o = 16; o; o >>= 1) cs += __shfl_xor_sync(0xffffffffu, cs, o);
    if (lane == 0) swred[w] = cs;

    {
        const float* src = g_eproj + (size_t)ind * ODIM;
        float* dst = out + OFF_ZQ + (size_t)r * ODIM;
#pragma unroll
        for (int c = t; c < ODIM; c += 256)
            dst[c] = src[c] + b_out[c];
    }
    __syncthreads();
    if (t == 0) {
        float tot = swred[0];
#pragma unroll
        for (int j = 1; j < 8; j++) tot += swred[j];
        atomicAdd(&g_scal[0], tot);
        out[OFF_IND + r] = (float)ind;
        atomicAdd(&g_bins[ind], 1.0f);
        atomicAdd(&g_scal[1], logf(Stot) - Ttot / Stot);
    }
}

// ---------------- ap column pass: 512 CTAs, unroll-8, conflict-free LUT ----------------
__global__ void __launch_bounds__(256)
ap_kernel() {
    __shared__ float lut[8192];
    __shared__ float sh_inv[256];
    int t = threadIdx.x, lane = t & 31;
    for (int i = t; i < 8192; i += 256) {
        int b = i >> 5;
        int q = (b < 128) ? b : b - 256;
        lut[i] = fast_exp(10.f * (float)q * QINV);
    }
    int c0 = (blockIdx.x * 256 + t) * 4;
    int r0 = blockIdx.y * 256;
    __syncthreads();
    sh_inv[t] = g_invS[r0 + t];
    __syncthreads();
    float a0 = 0.f, a1 = 0.f, a2 = 0.f, a3 = 0.f;
    const signed char* ep = g_d8 + (size_t)r0 * NE + c0;
#pragma unroll 8
    for (int j = 0; j < 256; j++) {
        uint32_t w = *(const uint32_t*)(ep + (size_t)j * NE);
        float inv = sh_inv[j];
        a0 = fmaf(lut[((w & 255u) << 5) | lane], inv, a0);
        a1 = fmaf(lut[(((w >> 8) & 255u) << 5) | lane], inv, a1);
        a2 = fmaf(lut[(((w >> 16) & 255u) << 5) | lane], inv, a2);
        a3 = fmaf(lut[((w >> 24) << 5) | lane], inv, a3);
    }
    atomicAdd(&g_ap[c0],     a0);
    atomicAdd(&g_ap[c0 + 1], a1);
    atomicAdd(&g_ap[c0 + 2], a2);
    atomicAdd(&g_ap[c0 + 3], a3);
}

// ---------------- merged e1 + scan (single block) ----------------
__global__ void e1scan_kernel(const float* __restrict__ cluster_size, float* __restrict__ out) {
    int t = threadIdx.x;
    __shared__ int sh[1024];
    __shared__ float shf[1024];
    int vals[8]; int s = 0; float csum = 0.f;
#pragma unroll
    for (int j = 0; j < 8; j++) {
        int i = t * 8 + j;
        float cn = cluster_size[i] * 0.99f + g_bins[i] * 0.01f;
        g_cluster_new[i] = cn;
        int ex = (cn < 0.1f);
        g_expired[i] = ex;
        out[OFF_CS + i] = ex ? 0.12f : cn;
        csum += cn;
        s += ex; vals[j] = s;
    }
    sh[t] = s; shf[t] = csum;
    __syncthreads();
    for (int off = 1; off < 1024; off <<= 1) {
        int v = (t >= off) ? sh[t - off] : 0;
        __syncthreads();
        sh[t] += v;
        __syncthreads();
    }
    for (int ss = 512; ss > 0; ss >>= 1) { if (t < ss) shf[t] += shf[t+ss]; __syncthreads(); }
    if (t == 0) g_scal[2] = shf[0];
    int excl = (t > 0) ? sh[t-1] : 0;
#pragma unroll
    for (int j = 0; j < 8; j++) {
        int cum = excl + vals[j];
        int idx = cum - 1; if (idx < 0) idx = 0;
        g_sampidx[t*8 + j] = idx;
    }
}

__global__ void e3_kernel(const float* __restrict__ embed_avg, float* __restrict__ out) {
    int c = blockIdx.x, k = threadIdx.x;
    float ea = embed_avg[(size_t)c * EDIM + k] * 0.99f + g_embed_sum[(size_t)c * EDIM + k] * 0.01f;
    float total = g_scal[2];
    float cn = g_cluster_new[c];
    float cs = (cn + 1e-5f) / (total + (float)NE * 1e-5f) * total;
    float en = ea / cs;
    float ef, eaf;
    if (g_expired[c]) {
        float sv = g_xn[(size_t)g_sampidx[c] * EDIM + k];
        ef = sv; eaf = sv * 0.12f;
    } else { ef = en; eaf = ea; }
    out[OFF_EMB  + (size_t)c * EDIM + k] = ef;
    out[OFF_EAVG + (size_t)c * EDIM + k] = eaf;
}

__global__ void scalars_kernel(float* __restrict__ out) {
    int t = threadIdx.x;
    __shared__ float sh[1024];
    float local = 0.f;
#pragma unroll
    for (int j = 0; j < 8; j++) {
        float ap = g_ap[t*8 + j] * (1.0f / (float)NTOK);
        local -= ap * logf(ap);
    }
    sh[t] = local;
    __syncthreads();
    for (int s = 512; s > 0; s >>= 1) { if (t < s) sh[t] += sh[t+s]; __syncthreads(); }
    if (t == 0) {
        float ent_max = sh[0];
        float commit  = g_scal[0] / ((float)NTOK * (float)EDIM);
        out[OFF_LOSS]   = commit - ent_max;
        out[OFF_ENTMIN] = g_scal[1] / (float)NTOK;
        out[OFF_COMMIT] = commit;
    }
}

// ---------------- launch ----------------
extern "C" void kernel_launch(void* const* d_in, const int* in_sizes, int n_in,
                              void* d_out, int out_size) {
    const float* x         = (const float*)d_in[0];
    const float* W_in      = (const float*)d_in[1];
    const float* b_in      = (const float*)d_in[2];
    const float* W_out     = (const float*)d_in[3];
    const float* b_out     = (const float*)d_in[4];
    const float* embed     = (const float*)d_in[5];
    const float* embed_avg = (const float*)d_in[6];
    const float* cluster   = (const float*)d_in[7];
    float* out = (float*)d_out;

    void *p_xn=nullptr, *p_a=nullptr, *p_eh=nullptr, *p_el=nullptr, *p_wh=nullptr, *p_wl=nullptr;
    cudaGetSymbolAddress(&p_xn, g_xn);
    cudaGetSymbolAddress(&p_a, g_a);
    cudaGetSymbolAddress(&p_eh, g_eh);
    cudaGetSymbolAddress(&p_el, g_el);
    cudaGetSymbolAddress(&p_wh, g_wh);
    cudaGetSymbolAddress(&p_wl, g_wl);

    cudaFuncSetAttribute(mma_d_kernel, cudaFuncAttributeMaxDynamicSharedMemorySize, SMEM_MMA);
    cudaFuncSetAttribute(eproj_kernel, cudaFuncAttributeMaxDynamicSharedMemorySize, SMEM_EP);

    conv_split_kernel<<<NE*EDIM/8/256, 256>>>(embed, (__nv_bfloat16*)p_eh,
                                              (__nv_bfloat16*)p_el);               // 1
    gemm_l2n_kernel<<<NTOK/64, 256>>>(x, W_in, b_in, (float*)p_xn,
                                      (__nv_bfloat16*)p_a);                        // 2 (fused l2norm)
    zero_kernel<<<8192, 256>>>();                                                  // 3
    mma_d_kernel<<<dim3(NE/128, NTOK/128), 256, SMEM_MMA>>>();                     // 4 <- profile
    conv_split_kernel<<<ODIM*EDIM/8/256, 256>>>(W_out, (__nv_bfloat16*)p_wh,
                                                (__nv_bfloat16*)p_wl);             // 5
    eproj_kernel<<<dim3(ODIM/128, NE/128), 256, SMEM_EP>>>();                      // 6
    reduce_partials_kernel<<<NTOK/256, 256>>>();                                   // 7
    row_finalize_kernel<<<NTOK, 256>>>(embed, b_out, out);                         // 8
    ap_kernel<<<dim3(NE/1024, NTOK/256), 256>>>();                                 // 9
    e1scan_kernel<<<1, 1024>>>(cluster, out);                                      // 10
    scalars_kernel<<<1, 1024>>>(out);                                              // 11
    e3_kernel<<<NE, 256>>>(embed_avg, out);                                        // 12
}